// round 9
// baseline (speedup 1.0000x reference)
#include <cuda_runtime.h>
#include <cuda_bf16.h>
#include <math.h>
#include <stdint.h>

// Problem constants
#define B_      1
#define S_      2048
#define H_      4096
#define NH_     32
#define NKV_    8
#define HD_     128
#define QKV_O   ((NH_ + 2 * NKV_) * HD_)   // 6144
#define Q_END   (NH_ * HD_)                // 4096
#define K_END   (Q_END + NKV_ * HD_)       // 5120

// ---------------------------------------------------------------------------
// Scratch (no allocations allowed)
// ---------------------------------------------------------------------------
__device__ float g_qkv[S_ * QKV_O];     // fp32 QKV   [2048, 6144]
__device__ float g_attn[S_ * H_];       // fp32 attn  [2048, 4096]

// int8 2-limb operands (x ~= step*(256*h + l))
__device__ signed char g_hid_h8[S_ * H_];
__device__ signed char g_hid_l8[S_ * H_];
__device__ signed char g_wqkv_h8[QKV_O * H_];
__device__ signed char g_wqkv_l8[QKV_O * H_];
__device__ signed char g_wo_h8[H_ * H_];
__device__ signed char g_wo_l8[H_ * H_];
__device__ signed char g_attn_h8[S_ * H_];
__device__ signed char g_attn_l8[S_ * H_];

// bf16 splits for attention
__device__ __nv_bfloat16 g_q_hi[S_ * H_];
__device__ __nv_bfloat16 g_q_lo[S_ * H_];
__device__ __nv_bfloat16 g_k_hi[S_ * NKV_ * HD_];
__device__ __nv_bfloat16 g_k_lo[S_ * NKV_ * HD_];
__device__ __nv_bfloat16 g_v_hi[S_ * NKV_ * HD_];
__device__ __nv_bfloat16 g_v_lo[S_ * NKV_ * HD_];

// scales: [0]=hidden [1]=Wqkv [2]=Wo [3]=attn  (maxabs as float bits)
__device__ unsigned g_scales[4];

// ---------------------------------------------------------------------------
// Baseline-ISA PTX helpers
// ---------------------------------------------------------------------------
__device__ __forceinline__ uint32_t smem_u32(const void* p) {
    uint32_t a;
    asm("{ .reg .u64 t; cvta.to.shared.u64 t, %1; cvt.u32.u64 %0, t; }"
        : "=r"(a) : "l"(p));
    return a;
}

#define CP_ASYNC16(dst, src) \
    asm volatile("cp.async.cg.shared.global [%0], [%1], 16;" \
        :: "r"(dst), "l"(src) : "memory")
#define CP_COMMIT() asm volatile("cp.async.commit_group;" ::: "memory")
#define CP_WAIT(n)  asm volatile("cp.async.wait_group %0;" :: "n"(n) : "memory")

#define LDSM_X4(r0, r1, r2, r3, addr) \
    asm volatile("ldmatrix.sync.aligned.m8n8.x4.shared.b16 {%0,%1,%2,%3}, [%4];" \
        : "=r"(r0), "=r"(r1), "=r"(r2), "=r"(r3) : "r"(addr))

#define LDSM_X4_T(r0, r1, r2, r3, addr) \
    asm volatile("ldmatrix.sync.aligned.m8n8.x4.trans.shared.b16 {%0,%1,%2,%3}, [%4];" \
        : "=r"(r0), "=r"(r1), "=r"(r2), "=r"(r3) : "r"(addr))

#define MMA_BF16(d, a, b0, b1) \
    asm volatile("mma.sync.aligned.m16n8k16.row.col.f32.bf16.bf16.f32 " \
        "{%0,%1,%2,%3}, {%4,%5,%6,%7}, {%8,%9}, {%0,%1,%2,%3};" \
        : "+f"((d)[0]), "+f"((d)[1]), "+f"((d)[2]), "+f"((d)[3]) \
        : "r"((a)[0]), "r"((a)[1]), "r"((a)[2]), "r"((a)[3]), "r"(b0), "r"(b1))

#define MMA_S8(d, a, b0, b1) \
    asm volatile("mma.sync.aligned.m16n8k32.row.col.s32.s8.s8.s32 " \
        "{%0,%1,%2,%3}, {%4,%5,%6,%7}, {%8,%9}, {%0,%1,%2,%3};" \
        : "+r"((d)[0]), "+r"((d)[1]), "+r"((d)[2]), "+r"((d)[3]) \
        : "r"((a)[0]), "r"((a)[1]), "r"((a)[2]), "r"((a)[3]), "r"(b0), "r"(b1))

__device__ __forceinline__ uint32_t pack_bf16(float x, float y) {
    __nv_bfloat162 h = __floats2bfloat162_rn(x, y);
    return *(uint32_t*)&h;
}

// Packed tile swizzle: tile rows of 64B packed 2-per-128B smem row, 16B slot
// XOR-swizzled.  Conflict-free for cp.async stores + all ldmatrix phases.
__device__ __forceinline__ uint32_t tile_off(int row, int unit) {
    uint32_t off = (uint32_t)((row >> 1) * 128 + (row & 1) * 64 + unit * 16);
    return off ^ ((off >> 3) & 0x70);
}

// ---------------------------------------------------------------------------
// maxabs reduction (atomicMax on abs-float bits)
// ---------------------------------------------------------------------------
__global__ void maxabs_kernel(const float4* __restrict__ x, int n4,
                              unsigned* __restrict__ out)
{
    float m = 0.0f;
    for (int i = blockIdx.x * blockDim.x + threadIdx.x; i < n4;
         i += gridDim.x * blockDim.x) {
        float4 v = x[i];
        m = fmaxf(m, fmaxf(fmaxf(fabsf(v.x), fabsf(v.y)),
                           fmaxf(fabsf(v.z), fabsf(v.w))));
    }
#pragma unroll
    for (int off = 16; off >= 1; off >>= 1)
        m = fmaxf(m, __shfl_xor_sync(0xffffffffu, m, off));
    if ((threadIdx.x & 31) == 0)
        atomicMax(out, __float_as_uint(m));
}

// ---------------------------------------------------------------------------
// fp32 -> 2-limb int8: q = round(x*32512/max) in [-32512,32512],
// q = 256*h + l exactly, h,l int8.
// ---------------------------------------------------------------------------
__global__ void quant_kernel(const float4* __restrict__ x, int n4,
                             const unsigned* __restrict__ mx,
                             char4* __restrict__ hi, char4* __restrict__ lo)
{
    int i = blockIdx.x * blockDim.x + threadIdx.x;
    if (i >= n4) return;
    float inv = 32512.0f / fmaxf(__uint_as_float(*mx), 1e-20f);
    float4 v = x[i];
    int q0 = min(32512, max(-32512, __float2int_rn(v.x * inv)));
    int q1 = min(32512, max(-32512, __float2int_rn(v.y * inv)));
    int q2 = min(32512, max(-32512, __float2int_rn(v.z * inv)));
    int q3 = min(32512, max(-32512, __float2int_rn(v.w * inv)));
    int h0 = (q0 + 128) >> 8, h1 = (q1 + 128) >> 8;
    int h2 = (q2 + 128) >> 8, h3 = (q3 + 128) >> 8;
    hi[i] = make_char4((signed char)h0, (signed char)h1,
                       (signed char)h2, (signed char)h3);
    lo[i] = make_char4((signed char)(q0 - (h0 << 8)), (signed char)(q1 - (h1 << 8)),
                       (signed char)(q2 - (h2 << 8)), (signed char)(q3 - (h3 << 8)));
}

// ---------------------------------------------------------------------------
// int8 2-limb EXACT GEMM via mma.sync.m16n8k32.s8:
//   C = sA*sB*(65536*hh + 256*(hl+lh) + ll),  A[M,K] * B[N,K]^T
// CTA tile 64x64, 8 warps (2m x 4n), warp tile 32x16.
// BK=64 chunks, swizzled 64B-row tiles, 4-stage cp.async pipeline,
// one __syncthreads per chunk, 2 CTAs/SM.
// ---------------------------------------------------------------------------
#define T8   4096                   // 64 rows * 64B per term-tile
#define STG8 16384                  // A(h,l) + B(h,l)
#define IMMA_STAGES 4
#define IMMA_SMEM (IMMA_STAGES * STG8)   // 65536

__global__ __launch_bounds__(256, 2) void gemm_imma_kernel(
    const signed char* __restrict__ Ah, const signed char* __restrict__ Al,
    const signed char* __restrict__ Bh, const signed char* __restrict__ Bl,
    float* __restrict__ C, int N, int K, int Mtiles,
    const unsigned* __restrict__ sA, const unsigned* __restrict__ sB)
{
    extern __shared__ __align__(128) char smem[];
    const uint32_t sbase = smem_u32(smem);
    const int tid = threadIdx.x;
    const int wid = tid >> 5;
    const int lane = tid & 31;
    const int m0 = (blockIdx.x % Mtiles) * 64;
    const int n0 = (blockIdx.x / Mtiles) * 64;
    const int NC = K / 64;

    const int warp_m = wid & 1;     // 0..1 (32 rows)
    const int warp_n = wid >> 1;    // 0..3 (16 cols)
    const int q = lane >> 3;
    const int r = lane & 7;

    int hh[2][2][4], mid[2][2][4], ll[2][2][4];
#pragma unroll
    for (int mt = 0; mt < 2; mt++)
#pragma unroll
        for (int nt = 0; nt < 2; nt++)
#pragma unroll
            for (int e = 0; e < 4; e++) {
                hh[mt][nt][e] = 0; mid[mt][nt][e] = 0; ll[mt][nt][e] = 0;
            }

    auto load_stage = [&](int stage, int c) {
        const uint32_t st = sbase + (uint32_t)stage * STG8;
#pragma unroll
        for (int i = 0; i < 2; i++) {              // A: 512 x 16B
            int g = tid + i * 256;
            int term = g >> 8;
            int rem = g & 255;
            int row = rem >> 2;
            int u = rem & 3;
            const signed char* src = (term ? Al : Ah)
                + (size_t)(m0 + row) * K + c * 64 + u * 16;
            CP_ASYNC16(st + (uint32_t)term * T8 + tile_off(row, u), src);
        }
#pragma unroll
        for (int i = 0; i < 2; i++) {              // B: 512 x 16B
            int g = tid + i * 256;
            int term = g >> 8;
            int rem = g & 255;
            int row = rem >> 2;
            int u = rem & 3;
            const signed char* src = (term ? Bl : Bh)
                + (size_t)(n0 + row) * K + c * 64 + u * 16;
            CP_ASYNC16(st + 2 * T8 + (uint32_t)term * T8 + tile_off(row, u), src);
        }
        CP_COMMIT();
    };

    // Prologue: 3 chunks ahead (one group per chunk, always)
    load_stage(0, 0);
    if (NC > 1) load_stage(1, 1); else CP_COMMIT();
    if (NC > 2) load_stage(2, 2); else CP_COMMIT();

    int stage = 0;
    for (int c = 0; c < NC; c++) {
        CP_WAIT(2);          // groups complete through chunk c
        __syncthreads();     // all warps done computing stage (c-1)%4
        if (c + 3 < NC) load_stage((stage + 3) & 3, c + 3);
        else CP_COMMIT();    // keep group count aligned

        const uint32_t st = sbase + (uint32_t)stage * STG8;
        const uint32_t aH = st, aL = st + T8;
        const uint32_t bH = st + 2 * T8, bL = st + 3 * T8;

#pragma unroll
        for (int kstep = 0; kstep < 2; kstep++) {
            uint32_t bhf[4], blf[4];
            {
                int brow = warp_n * 16 + (q >> 1) * 8 + r;
                uint32_t boff = tile_off(brow, kstep * 2 + (q & 1));
                LDSM_X4(bhf[0], bhf[1], bhf[2], bhf[3], bH + boff);
                LDSM_X4(blf[0], blf[1], blf[2], blf[3], bL + boff);
            }
            const int aunit = kstep * 2 + (q >> 1);
#pragma unroll
            for (int mt = 0; mt < 2; mt++) {
                uint32_t ahf[4], alf[4];
                int arow = warp_m * 32 + mt * 16 + (q & 1) * 8 + r;
                uint32_t aoff = tile_off(arow, aunit);
                LDSM_X4(ahf[0], ahf[1], ahf[2], ahf[3], aH + aoff);
                LDSM_X4(alf[0], alf[1], alf[2], alf[3], aL + aoff);

                MMA_S8(hh[mt][0],  ahf, bhf[0], bhf[1]);
                MMA_S8(hh[mt][1],  ahf, bhf[2], bhf[3]);
                MMA_S8(mid[mt][0], ahf, blf[0], blf[1]);
                MMA_S8(mid[mt][1], ahf, blf[2], blf[3]);
                MMA_S8(mid[mt][0], alf, bhf[0], bhf[1]);
                MMA_S8(mid[mt][1], alf, bhf[2], bhf[3]);
                MMA_S8(ll[mt][0],  alf, blf[0], blf[1]);
                MMA_S8(ll[mt][1],  alf, blf[2], blf[3]);
            }
        }
        stage = (stage + 1) & 3;
    }

    // Epilogue: exact dequantize, fp32 store
    const float sAB = (__uint_as_float(__ldg(sA)) / 32512.0f)
                    * (__uint_as_float(__ldg(sB)) / 32512.0f);
    const int gp = lane >> 2;
    const int tg = lane & 3;
#pragma unroll
    for (int mt = 0; mt < 2; mt++) {
#pragma unroll
        for (int nt = 0; nt < 2; nt++) {
            int row = m0 + warp_m * 32 + mt * 16 + gp;
            int col = n0 + warp_n * 16 + nt * 8 + tg * 2;
#pragma unroll
            for (int hf = 0; hf < 2; hf++) {
                float f0 = sAB * (65536.0f * (float)hh[mt][nt][2 * hf]
                                 + 256.0f * (float)mid[mt][nt][2 * hf]
                                 + (float)ll[mt][nt][2 * hf]);
                float f1 = sAB * (65536.0f * (float)hh[mt][nt][2 * hf + 1]
                                 + 256.0f * (float)mid[mt][nt][2 * hf + 1]
                                 + (float)ll[mt][nt][2 * hf + 1]);
                *(float2*)&C[(size_t)(row + hf * 8) * N + col] = make_float2(f0, f1);
            }
        }
    }
}

// ---------------------------------------------------------------------------
// RoPE + bf16 hi/lo conversion of Q,K.  One block per sequence position s.
// ---------------------------------------------------------------------------
__global__ __launch_bounds__(256) void rope_cvt_kernel(
    const float* __restrict__ qkv,
    __nv_bfloat16* __restrict__ qhi, __nv_bfloat16* __restrict__ qlo,
    __nv_bfloat16* __restrict__ khi, __nv_bfloat16* __restrict__ klo)
{
    __shared__ float cs[64], sn[64];
    const int s = blockIdx.x;
    const int tid = threadIdx.x;
    if (tid < 64) {
        double inv = exp(-((double)(2 * tid) / (double)HD_) * 9.210340371976184);
        double ang = (double)s * inv;
        double sv, cv;
        sincos(ang, &sv, &cv);
        cs[tid] = (float)cv;
        sn[tid] = (float)sv;
    }
    __syncthreads();

#pragma unroll
    for (int it = 0; it < 10; it++) {
        int g = tid + it * 256;
        int d2 = g & 63;
        int head = g >> 6;          // 0..39
        size_t base = (size_t)s * QKV_O + head * HD_;
        float x1 = qkv[base + d2];
        float x2 = qkv[base + 64 + d2];
        float c = cs[d2], si = sn[d2];
        float y1 = x1 * c - x2 * si;
        float y2 = x1 * si + x2 * c;

        __nv_bfloat16 h1 = __float2bfloat16_rn(y1);
        __nv_bfloat16 l1 = __float2bfloat16_rn(y1 - __bfloat162float(h1));
        __nv_bfloat16 h2 = __float2bfloat16_rn(y2);
        __nv_bfloat16 l2 = __float2bfloat16_rn(y2 - __bfloat162float(h2));

        if (head < NH_) {
            size_t o = (size_t)s * H_ + head * HD_;
            qhi[o + d2] = h1; qlo[o + d2] = l1;
            qhi[o + 64 + d2] = h2; qlo[o + 64 + d2] = l2;
        } else {
            size_t o = (size_t)s * (NKV_ * HD_) + (head - NH_) * HD_;
            khi[o + d2] = h1; klo[o + d2] = l1;
            khi[o + 64 + d2] = h2; klo[o + 64 + d2] = l2;
        }
    }
}

// V: strided split-convert out of g_qkv
__global__ void v_cvt_kernel(const float* __restrict__ qkv,
                             __nv_bfloat16* __restrict__ vhi,
                             __nv_bfloat16* __restrict__ vlo)
{
    int i = blockIdx.x * blockDim.x + threadIdx.x;
    const int n4 = S_ * NKV_ * HD_ / 4;
    if (i >= n4) return;
    int s = i >> 8;
    int col = (i & 255) * 4;
    const float* src = qkv + (size_t)s * QKV_O + K_END + col;
    float4 v = *(const float4*)src;
    __nv_bfloat16 h0 = __float2bfloat16_rn(v.x);
    __nv_bfloat16 h1 = __float2bfloat16_rn(v.y);
    __nv_bfloat16 h2 = __float2bfloat16_rn(v.z);
    __nv_bfloat16 h3 = __float2bfloat16_rn(v.w);
    size_t o = (size_t)s * (NKV_ * HD_) + col;
    *(__nv_bfloat162*)(vhi + o)     = __nv_bfloat162(h0, h1);
    *(__nv_bfloat162*)(vhi + o + 2) = __nv_bfloat162(h2, h3);
    *(__nv_bfloat162*)(vlo + o) = __nv_bfloat162(
        __float2bfloat16_rn(v.x - __bfloat162float(h0)),
        __float2bfloat16_rn(v.y - __bfloat162float(h1)));
    *(__nv_bfloat162*)(vlo + o + 2) = __nv_bfloat162(
        __float2bfloat16_rn(v.z - __bfloat162float(h2)),
        __float2bfloat16_rn(v.w - __bfloat162float(h3)));
}

// ---------------------------------------------------------------------------
// Flash attention via mma.sync, bf16x3 QK^T and bf16x3 PV, causal, GQA.
// ---------------------------------------------------------------------------
#define AP_ 136
#define APB_ 272
#define Q_COMP_B 17408
#define KV_COMP_B 8704
#define KV_STAGE_B (4 * KV_COMP_B)
#define ATTN_SMEM_BYTES (2 * Q_COMP_B + 2 * KV_STAGE_B)   // 104448

__global__ __launch_bounds__(128, 2) void flash_attn_mma_kernel(
    const __nv_bfloat16* __restrict__ qhi, const __nv_bfloat16* __restrict__ qlo,
    const __nv_bfloat16* __restrict__ khi, const __nv_bfloat16* __restrict__ klo,
    const __nv_bfloat16* __restrict__ vhi, const __nv_bfloat16* __restrict__ vlo,
    float* __restrict__ attn_out)
{
    extern __shared__ __align__(128) char smA[];
    const uint32_t sb = smem_u32(smA);
    const int qb = gridDim.x - 1 - blockIdx.x;   // heavy blocks first
    const int head = blockIdx.y;
    const int kvh = head >> 2;
    const int tid = threadIdx.x;
    const int wid = tid >> 5;
    const int lane = tid & 31;
    const int gp = lane >> 2;
    const int tg = lane & 3;
    const int q0 = qb * 64;

    const uint32_t Qhi_s = sb;
    const uint32_t Qlo_s = sb + Q_COMP_B;
    const uint32_t Stage_s = sb + 2 * Q_COMP_B;

#pragma unroll
    for (int i = 0; i < 16; i++) {
        int g = tid + i * 128;
        int comp = g >> 10;
        int rem = g & 1023;
        int row = rem >> 4;
        int u = rem & 15;
        const __nv_bfloat16* src = (comp ? qlo : qhi)
            + (size_t)(q0 + row) * H_ + head * HD_ + u * 8;
        uint32_t dst = (comp ? Qlo_s : Qhi_s) + (uint32_t)(row * APB_ + u * 16);
        CP_ASYNC16(dst, src);
    }
    CP_COMMIT();

    const int kb_max = 2 * qb + 1;

    auto load_kv = [&](int stage, int kb) {
        uint32_t st = Stage_s + (uint32_t)stage * KV_STAGE_B;
        const __nv_bfloat16* bases[4] = {khi, klo, vhi, vlo};
#pragma unroll
        for (int i = 0; i < 16; i++) {
            int g = tid + i * 128;
            int comp = g >> 9;
            int rem = g & 511;
            int row = rem >> 4;
            int u = rem & 15;
            const __nv_bfloat16* src = bases[comp]
                + (size_t)(kb * 32 + row) * (NKV_ * HD_) + kvh * HD_ + u * 8;
            CP_ASYNC16(st + (uint32_t)(comp * KV_COMP_B + row * APB_ + u * 16), src);
        }
        CP_COMMIT();
    };

    load_kv(0, 0);

    float O[16][4];
    float m_i[2] = {-1e30f, -1e30f};
    float l_i[2] = {0.0f, 0.0f};
#pragma unroll
    for (int nt = 0; nt < 16; nt++)
#pragma unroll
        for (int e = 0; e < 4; e++) O[nt][e] = 0.0f;

    const float scale = 0.08838834764831845f;

    for (int kb = 0; kb <= kb_max; kb++) {
        if (kb < kb_max) { load_kv((kb + 1) & 1, kb + 1); CP_WAIT(1); }
        else             { CP_WAIT(0); }
        __syncthreads();

        const uint32_t st = Stage_s + (uint32_t)(kb & 1) * KV_STAGE_B;
        const uint32_t Ks_hi = st;
        const uint32_t Ks_lo = st + KV_COMP_B;
        const uint32_t Vs_hi = st + 2 * KV_COMP_B;
        const uint32_t Vs_lo = st + 3 * KV_COMP_B;

        float S[4][4];
#pragma unroll
        for (int t = 0; t < 4; t++)
#pragma unroll
            for (int e = 0; e < 4; e++) S[t][e] = 0.0f;

#pragma unroll
        for (int kt = 0; kt < 8; kt++) {
            uint32_t aoff = (uint32_t)((wid * 16 + (lane & 15)) * APB_
                                       + (kt * 16 + (lane >> 4) * 8) * 2);
            uint32_t ahi[4], alo[4];
            LDSM_X4(ahi[0], ahi[1], ahi[2], ahi[3], Qhi_s + aoff);
            LDSM_X4(alo[0], alo[1], alo[2], alo[3], Qlo_s + aoff);

            uint32_t bh[2][4], bl[2][4];
#pragma unroll
            for (int pr = 0; pr < 2; pr++) {
                uint32_t boff = (uint32_t)((pr * 16 + (lane >> 4) * 8 + (lane & 7)) * APB_
                                           + (kt * 16 + ((lane >> 3) & 1) * 8) * 2);
                LDSM_X4(bh[pr][0], bh[pr][1], bh[pr][2], bh[pr][3], Ks_hi + boff);
                LDSM_X4(bl[pr][0], bl[pr][1], bl[pr][2], bl[pr][3], Ks_lo + boff);
            }
            MMA_BF16(S[0], ahi, bh[0][0], bh[0][1]);
            MMA_BF16(S[1], ahi, bh[0][2], bh[0][3]);
            MMA_BF16(S[2], ahi, bh[1][0], bh[1][1]);
            MMA_BF16(S[3], ahi, bh[1][2], bh[1][3]);

            MMA_BF16(S[0], ahi, bl[0][0], bl[0][1]);
            MMA_BF16(S[1], ahi, bl[0][2], bl[0][3]);
            MMA_BF16(S[2], ahi, bl[1][0], bl[1][1]);
            MMA_BF16(S[3], ahi, bl[1][2], bl[1][3]);

            MMA_BF16(S[0], alo, bh[0][0], bh[0][1]);
            MMA_BF16(S[1], alo, bh[0][2], bh[0][3]);
            MMA_BF16(S[2], alo, bh[1][0], bh[1][1]);
            MMA_BF16(S[3], alo, bh[1][2], bh[1][3]);
        }

        if (kb >= 2 * qb) {
#pragma unroll
            for (int t = 0; t < 4; t++) {
                int colb = kb * 32 + t * 8 + 2 * tg;
#pragma unroll
                for (int e = 0; e < 4; e++) {
                    int col = colb + (e & 1);
                    int row = q0 + wid * 16 + gp + ((e >= 2) ? 8 : 0);
                    S[t][e] = (col <= row) ? S[t][e] * scale : -1e30f;
                }
            }
        } else {
#pragma unroll
            for (int t = 0; t < 4; t++)
#pragma unroll
                for (int e = 0; e < 4; e++) S[t][e] *= scale;
        }

#pragma unroll
        for (int h = 0; h < 2; h++) {
            float mx = -1e30f;
#pragma unroll
            for (int t = 0; t < 4; t++)
                mx = fmaxf(mx, fmaxf(S[t][2 * h], S[t][2 * h + 1]));
            mx = fmaxf(mx, __shfl_xor_sync(0xffffffffu, mx, 1));
            mx = fmaxf(mx, __shfl_xor_sync(0xffffffffu, mx, 2));
            float m_new = fmaxf(m_i[h], mx);
            float alpha = __expf(m_i[h] - m_new);
            float sum = 0.0f;
#pragma unroll
            for (int t = 0; t < 4; t++) {
                S[t][2 * h]     = __expf(S[t][2 * h] - m_new);
                S[t][2 * h + 1] = __expf(S[t][2 * h + 1] - m_new);
                sum += S[t][2 * h] + S[t][2 * h + 1];
            }
            sum += __shfl_xor_sync(0xffffffffu, sum, 1);
            sum += __shfl_xor_sync(0xffffffffu, sum, 2);
            l_i[h] = l_i[h] * alpha + sum;
            m_i[h] = m_new;
#pragma unroll
            for (int nt = 0; nt < 16; nt++) {
                O[nt][2 * h] *= alpha;
                O[nt][2 * h + 1] *= alpha;
            }
        }

#pragma unroll
        for (int kt2 = 0; kt2 < 2; kt2++) {
            uint32_t phi[4], plo[4];
            {
                float* p0 = S[2 * kt2];
                float* p1 = S[2 * kt2 + 1];
                float h00 = __bfloat162float(__float2bfloat16_rn(p0[0]));
                float h01 = __bfloat162float(__float2bfloat16_rn(p0[1]));
                float h02 = __bfloat162float(__float2bfloat16_rn(p0[2]));
                float h03 = __bfloat162float(__float2bfloat16_rn(p0[3]));
                float h10 = __bfloat162float(__float2bfloat16_rn(p1[0]));
                float h11 = __bfloat162float(__float2bfloat16_rn(p1[1]));
                float h12 = __bfloat162float(__float2bfloat16_rn(p1[2]));
                float h13 = __bfloat162float(__float2bfloat16_rn(p1[3]));
                phi[0] = pack_bf16(h00, h01);
                phi[1] = pack_bf16(h02, h03);
                phi[2] = pack_bf16(h10, h11);
                phi[3] = pack_bf16(h12, h13);
                plo[0] = pack_bf16(p0[0] - h00, p0[1] - h01);
                plo[1] = pack_bf16(p0[2] - h02, p0[3] - h03);
                plo[2] = pack_bf16(p1[0] - h10, p1[1] - h11);
                plo[3] = pack_bf16(p1[2] - h12, p1[3] - h13);
            }
#pragma unroll
            for (int dq = 0; dq < 4; dq++) {
                uint32_t bh0[4], bl0[4], bh1[4], bl1[4];
#pragma unroll
                for (int half = 0; half < 2; half++) {
                    int dp = 2 * dq + half;
                    uint32_t voff = (uint32_t)((kt2 * 16 + ((lane >> 3) & 1) * 8 + (lane & 7)) * APB_
                                               + (dp * 16 + (lane >> 4) * 8) * 2);
                    if (half == 0) {
                        LDSM_X4_T(bh0[0], bh0[1], bh0[2], bh0[3], Vs_hi + voff);
                        LDSM_X4_T(bl0[0], bl0[1], bl0[2], bl0[3], Vs_lo + voff);
                    } else {
                        LDSM_X4_T(bh1[0], bh1[1], bh1[2], bh1[3], Vs_hi + voff);
                        LDSM_X4_T(bl1[0], bl1[1], bl1[2], bl1[3], Vs_lo + voff);
                    }
                }
                float* O0 = O[4 * dq + 0];
                float* O1 = O[4 * dq + 1];
                float* O2 = O[4 * dq + 2];
                float* O3 = O[4 * dq + 3];
                MMA_BF16(O0, phi, bh0[0], bh0[1]);
                MMA_BF16(O1, phi, bh0[2], bh0[3]);
                MMA_BF16(O2, phi, bh1[0], bh1[1]);
                MMA_BF16(O3, phi, bh1[2], bh1[3]);

                MMA_BF16(O0, phi, bl0[0], bl0[1]);
                MMA_BF16(O1, phi, bl0[2], bl0[3]);
                MMA_BF16(O2, phi, bl1[0], bl1[1]);
                MMA_BF16(O3, phi, bl1[2], bl1[3]);

                MMA_BF16(O0, plo, bh0[0], bh0[1]);
                MMA_BF16(O1, plo, bh0[2], bh0[3]);
                MMA_BF16(O2, plo, bh1[0], bh1[1]);
                MMA_BF16(O3, plo, bh1[2], bh1[3]);
            }
        }
        __syncthreads();
    }

#pragma unroll
    for (int h = 0; h < 2; h++) {
        float inv = 1.0f / l_i[h];
        int row = q0 + wid * 16 + gp + h * 8;
        float* orow = attn_out + (size_t)row * H_ + head * HD_;
#pragma unroll
        for (int nt = 0; nt < 16; nt++) {
            *(float2*)&orow[nt * 8 + 2 * tg] =
                make_float2(O[nt][2 * h] * inv, O[nt][2 * h + 1] * inv);
        }
    }
}

// ---------------------------------------------------------------------------
extern "C" void kernel_launch(void* const* d_in, const int* in_sizes, int n_in,
                              void* d_out, int out_size)
{
    const float* hidden = (const float*)d_in[0];   // [1,2048,4096]
    const float* Wqkv   = (const float*)d_in[1];   // [6144,4096]
    const float* Wo     = (const float*)d_in[2];   // [4096,4096]
    float* out = (float*)d_out;                    // [1,2048,4096]

    float *qkv_ptr, *attn_ptr;
    signed char *hid_h8, *hid_l8, *wqkv_h8, *wqkv_l8, *wo_h8, *wo_l8, *attn_h8, *attn_l8;
    __nv_bfloat16 *q_hi, *q_lo, *k_hi, *k_lo, *v_hi, *v_lo;
    unsigned* scales;
    cudaGetSymbolAddress((void**)&qkv_ptr, g_qkv);
    cudaGetSymbolAddress((void**)&attn_ptr, g_attn);
    cudaGetSymbolAddress((void**)&hid_h8, g_hid_h8);
    cudaGetSymbolAddress((void**)&hid_l8, g_hid_l8);
    cudaGetSymbolAddress((void**)&wqkv_h8, g_wqkv_h8);
    cudaGetSymbolAddress((void**)&wqkv_l8, g_wqkv_l8);
    cudaGetSymbolAddress((void**)&wo_h8, g_wo_h8);
    cudaGetSymbolAddress((void**)&wo_l8, g_wo_l8);
    cudaGetSymbolAddress((void**)&attn_h8, g_attn_h8);
    cudaGetSymbolAddress((void**)&attn_l8, g_attn_l8);
    cudaGetSymbolAddress((void**)&q_hi, g_q_hi);
    cudaGetSymbolAddress((void**)&q_lo, g_q_lo);
    cudaGetSymbolAddress((void**)&k_hi, g_k_hi);
    cudaGetSymbolAddress((void**)&k_lo, g_k_lo);
    cudaGetSymbolAddress((void**)&v_hi, g_v_hi);
    cudaGetSymbolAddress((void**)&v_lo, g_v_lo);
    cudaGetSymbolAddress((void**)&scales, g_scales);

    cudaFuncSetAttribute(gemm_imma_kernel,
                         cudaFuncAttributeMaxDynamicSharedMemorySize, IMMA_SMEM);
    cudaFuncSetAttribute(flash_attn_mma_kernel,
                         cudaFuncAttributeMaxDynamicSharedMemorySize, ATTN_SMEM_BYTES);

    // 0) zero scales, maxabs + quantize inputs
    cudaMemsetAsync(scales, 0, 4 * sizeof(unsigned));
    {
        int n4;
        n4 = (S_ * H_) / 4;
        maxabs_kernel<<<1024, 256>>>((const float4*)hidden, n4, scales + 0);
        n4 = (QKV_O * H_) / 4;
        maxabs_kernel<<<2048, 256>>>((const float4*)Wqkv, n4, scales + 1);
        n4 = (H_ * H_) / 4;
        maxabs_kernel<<<2048, 256>>>((const float4*)Wo, n4, scales + 2);

        n4 = (S_ * H_) / 4;
        quant_kernel<<<(n4 + 255) / 256, 256>>>((const float4*)hidden, n4,
            scales + 0, (char4*)hid_h8, (char4*)hid_l8);
        n4 = (QKV_O * H_) / 4;
        quant_kernel<<<(n4 + 255) / 256, 256>>>((const float4*)Wqkv, n4,
            scales + 1, (char4*)wqkv_h8, (char4*)wqkv_l8);
        n4 = (H_ * H_) / 4;
        quant_kernel<<<(n4 + 255) / 256, 256>>>((const float4*)Wo, n4,
            scales + 2, (char4*)wo_h8, (char4*)wo_l8);
    }

    // 1) QKV projection (int8 exact 2-limb): [2048,6144] fp32
    {
        int mt = S_ / 64, nt = QKV_O / 64;
        gemm_imma_kernel<<<mt * nt, 256, IMMA_SMEM>>>(
            hid_h8, hid_l8, wqkv_h8, wqkv_l8, qkv_ptr, QKV_O, H_, mt,
            scales + 0, scales + 1);
    }

    // 2) RoPE + bf16 splits of Q,K; V split
    {
        rope_cvt_kernel<<<S_, 256>>>(qkv_ptr, q_hi, q_lo, k_hi, k_lo);
        int n4 = (S_ * NKV_ * HD_) / 4;
        v_cvt_kernel<<<(n4 + 255) / 256, 256>>>(qkv_ptr, v_hi, v_lo);
    }

    // 3) Flash attention (HMMA bf16x3) -> fp32 attn
    {
        dim3 grid(S_ / 64, NH_);
        flash_attn_mma_kernel<<<grid, 128, ATTN_SMEM_BYTES>>>(
            q_hi, q_lo, k_hi, k_lo, v_hi, v_lo, attn_ptr);
    }

    // 4) maxabs + quantize attn output
    {
        int n4 = (S_ * H_) / 4;
        maxabs_kernel<<<1024, 256>>>((const float4*)attn_ptr, n4, scales + 3);
        quant_kernel<<<(n4 + 255) / 256, 256>>>((const float4*)attn_ptr, n4,
            scales + 3, (char4*)attn_h8, (char4*)attn_l8);
    }

    // 5) Output projection (int8 exact 2-limb): [2048,4096]
    {
        int mt = S_ / 64, nt = H_ / 64;
        gemm_imma_kernel<<<mt * nt, 256, IMMA_SMEM>>>(
            attn_h8, attn_l8, wo_h8, wo_l8, out, H_, H_, mt,
            scales + 3, scales + 2);
    }
}

// round 10
// speedup vs baseline: 3.0887x; 3.0887x over previous
#include <cuda_runtime.h>
#include <cuda_bf16.h>
#include <math.h>
#include <stdint.h>

// Problem constants
#define B_      1
#define S_      2048
#define H_      4096
#define NH_     32
#define NKV_    8
#define HD_     128
#define QKV_O   ((NH_ + 2 * NKV_) * HD_)   // 6144
#define Q_END   (NH_ * HD_)                // 4096
#define K_END   (Q_END + NKV_ * HD_)       // 5120

// ---------------------------------------------------------------------------
// Scratch (no allocations allowed)
// ---------------------------------------------------------------------------
__device__ float g_qkv[S_ * QKV_O];     // fp32 QKV   [2048, 6144]

__device__ __nv_bfloat16 g_hid_hi[S_ * H_];
__device__ __nv_bfloat16 g_hid_lo[S_ * H_];
__device__ __nv_bfloat16 g_wqkv_hi[QKV_O * H_];
__device__ __nv_bfloat16 g_wqkv_lo[QKV_O * H_];
__device__ __nv_bfloat16 g_wo_hi[H_ * H_];
__device__ __nv_bfloat16 g_wo_lo[H_ * H_];
__device__ __nv_bfloat16 g_attn_hi[S_ * H_];
__device__ __nv_bfloat16 g_attn_lo[S_ * H_];

__device__ __nv_bfloat16 g_q_hi[S_ * H_];            // RoPE'd Q  [2048, 4096]
__device__ __nv_bfloat16 g_q_lo[S_ * H_];
__device__ __nv_bfloat16 g_k_hi[S_ * NKV_ * HD_];    // RoPE'd K  [2048, 1024]
__device__ __nv_bfloat16 g_k_lo[S_ * NKV_ * HD_];
__device__ __nv_bfloat16 g_v_hi[S_ * NKV_ * HD_];    // V         [2048, 1024]
__device__ __nv_bfloat16 g_v_lo[S_ * NKV_ * HD_];

__device__ unsigned g_counters[4];      // work-stealing tile counters

// ---------------------------------------------------------------------------
// Baseline-ISA PTX helpers
// ---------------------------------------------------------------------------
__device__ __forceinline__ uint32_t smem_u32(const void* p) {
    uint32_t a;
    asm("{ .reg .u64 t; cvta.to.shared.u64 t, %1; cvt.u32.u64 %0, t; }"
        : "=r"(a) : "l"(p));
    return a;
}

#define CP_ASYNC16(dst, src) \
    asm volatile("cp.async.cg.shared.global [%0], [%1], 16;" \
        :: "r"(dst), "l"(src) : "memory")
#define CP_COMMIT() asm volatile("cp.async.commit_group;" ::: "memory")
#define CP_WAIT(n)  asm volatile("cp.async.wait_group %0;" :: "n"(n) : "memory")

#define LDSM_X4(r0, r1, r2, r3, addr) \
    asm volatile("ldmatrix.sync.aligned.m8n8.x4.shared.b16 {%0,%1,%2,%3}, [%4];" \
        : "=r"(r0), "=r"(r1), "=r"(r2), "=r"(r3) : "r"(addr))

#define LDSM_X4_T(r0, r1, r2, r3, addr) \
    asm volatile("ldmatrix.sync.aligned.m8n8.x4.trans.shared.b16 {%0,%1,%2,%3}, [%4];" \
        : "=r"(r0), "=r"(r1), "=r"(r2), "=r"(r3) : "r"(addr))

#define MMA_BF16(d, a, b0, b1) \
    asm volatile("mma.sync.aligned.m16n8k16.row.col.f32.bf16.bf16.f32 " \
        "{%0,%1,%2,%3}, {%4,%5,%6,%7}, {%8,%9}, {%0,%1,%2,%3};" \
        : "+f"((d)[0]), "+f"((d)[1]), "+f"((d)[2]), "+f"((d)[3]) \
        : "r"((a)[0]), "r"((a)[1]), "r"((a)[2]), "r"((a)[3]), "r"(b0), "r"(b1))

__device__ __forceinline__ uint32_t pack_bf16(float x, float y) {
    __nv_bfloat162 h = __floats2bfloat162_rn(x, y);
    return *(uint32_t*)&h;
}

// Packed tile swizzle (conflict-free for cp.async stores + ldmatrix phases)
__device__ __forceinline__ uint32_t tile_off(int row, int unit) {
    uint32_t off = (uint32_t)((row >> 1) * 128 + (row & 1) * 64 + unit * 16);
    return off ^ ((off >> 3) & 0x70);
}

// ---------------------------------------------------------------------------
// fp32 -> (bf16 hi, bf16 lo) split conversion. n4 = n/4 float4 groups.
// ---------------------------------------------------------------------------
__global__ void cvt_split_kernel(const float* __restrict__ x,
                                 __nv_bfloat16* __restrict__ hi,
                                 __nv_bfloat16* __restrict__ lo, int n4)
{
    int i = blockIdx.x * blockDim.x + threadIdx.x;
    if (i >= n4) return;
    float4 v = ((const float4*)x)[i];
    __nv_bfloat16 h0 = __float2bfloat16_rn(v.x);
    __nv_bfloat16 h1 = __float2bfloat16_rn(v.y);
    __nv_bfloat16 h2 = __float2bfloat16_rn(v.z);
    __nv_bfloat16 h3 = __float2bfloat16_rn(v.w);
    __nv_bfloat16 l0 = __float2bfloat16_rn(v.x - __bfloat162float(h0));
    __nv_bfloat16 l1 = __float2bfloat16_rn(v.y - __bfloat162float(h1));
    __nv_bfloat16 l2 = __float2bfloat16_rn(v.z - __bfloat162float(h2));
    __nv_bfloat16 l3 = __float2bfloat16_rn(v.w - __bfloat162float(h3));
    ((__nv_bfloat162*)hi)[i * 2 + 0] = __nv_bfloat162(h0, h1);
    ((__nv_bfloat162*)hi)[i * 2 + 1] = __nv_bfloat162(h2, h3);
    ((__nv_bfloat162*)lo)[i * 2 + 0] = __nv_bfloat162(l0, l1);
    ((__nv_bfloat162*)lo)[i * 2 + 1] = __nv_bfloat162(l2, l3);
}

// ---------------------------------------------------------------------------
// bf16x3 GEMM via mma.sync (HMMA):  C[M,N] = A[M,K] * B[N,K]^T
// Packed-swizzled 32KB stages, 3-stage cp.async pipeline, one sync per chunk.
// PERSISTENT CTAs with dynamic work-stealing over 128x128 tiles.
// ---------------------------------------------------------------------------
#define TILE_B   8192               // 128 rows * 64B (packed, swizzled)
#define STAGE_B  (4 * TILE_B)       // 32768
#define GEMM_STAGES 3
#define GEMM_SMEM_BYTES (GEMM_STAGES * STAGE_B)   // 98304

__global__ __launch_bounds__(256, 2) void gemm_mma_kernel(
    const __nv_bfloat16* __restrict__ Ahi, const __nv_bfloat16* __restrict__ Alo,
    const __nv_bfloat16* __restrict__ Bhi, const __nv_bfloat16* __restrict__ Blo,
    float* __restrict__ C, int N, int K, int Mtiles, int total_tiles,
    unsigned* __restrict__ counter)
{
    extern __shared__ __align__(128) char smem[];
    __shared__ unsigned s_tile;
    const uint32_t sbase = smem_u32(smem);
    const int tid = threadIdx.x;
    const int wid = tid >> 5;
    const int lane = tid & 31;
    const int NC = K / 32;

    const int warp_m = wid & 1;
    const int warp_n = wid >> 1;
    const int q = lane >> 3;
    const int r = lane & 7;
    const int gp = lane >> 2;
    const int tg = lane & 3;

    for (;;) {
        if (tid == 0) s_tile = atomicAdd(counter, 1u);
        __syncthreads();                 // tile uniform + prev compute done
        const unsigned t = s_tile;
        if (t >= (unsigned)total_tiles) return;
        const int m0 = ((int)t % Mtiles) * 128;
        const int n0 = ((int)t / Mtiles) * 128;

        const __nv_bfloat16* srcs[4] = {Ahi, Alo, Bhi, Blo};
        const int row0s[4] = {m0, m0, n0, n0};

        float acc[4][4][4];
#pragma unroll
        for (int mt = 0; mt < 4; mt++)
#pragma unroll
            for (int nt = 0; nt < 4; nt++)
#pragma unroll
                for (int e = 0; e < 4; e++) acc[mt][nt][e] = 0.0f;

        auto load_stage = [&](int stage, int c) {
            const uint32_t st = sbase + (uint32_t)stage * STAGE_B;
#pragma unroll
            for (int i = 0; i < 8; i++) {
                int g = tid + i * 256;
                int sel = g >> 9;
                int rem = g & 511;
                int row = rem >> 2;
                int u = rem & 3;
                const char* gsrc = (const char*)(srcs[sel] + (size_t)(row0s[sel] + row) * K)
                                   + c * 64 + u * 16;
                uint32_t dst = st + (uint32_t)sel * TILE_B + tile_off(row, u);
                CP_ASYNC16(dst, gsrc);
            }
            CP_COMMIT();
        };

        load_stage(0, 0);
        load_stage(1, 1);

        int stage = 0;
        for (int c = 0; c < NC; c++) {
            if (c + 1 < NC) { CP_WAIT(1); }   // chunk c landed
            else           { CP_WAIT(0); }    // tail: everything landed
            __syncthreads();
            if (c + 2 < NC) load_stage((stage + 2) % GEMM_STAGES, c + 2);

            const uint32_t st = sbase + (uint32_t)stage * STAGE_B;
            const uint32_t aBase = st;
            const uint32_t bBase = st + 2 * TILE_B;

#pragma unroll
            for (int kstep = 0; kstep < 2; kstep++) {
                uint32_t bh0[4], bh1[4], bl0[4], bl1[4];
                const int bunit = kstep * 2 + (q & 1);
                {
                    int brow0 = warp_n * 32 + (q >> 1) * 8 + r;
                    uint32_t a0 = bBase + tile_off(brow0, bunit);
                    LDSM_X4(bh0[0], bh0[1], bh0[2], bh0[3], a0);
                    LDSM_X4(bl0[0], bl0[1], bl0[2], bl0[3], a0 + TILE_B);
                    uint32_t a1 = bBase + tile_off(brow0 + 16, bunit);
                    LDSM_X4(bh1[0], bh1[1], bh1[2], bh1[3], a1);
                    LDSM_X4(bl1[0], bl1[1], bl1[2], bl1[3], a1 + TILE_B);
                }
                const int aunit = kstep * 2 + (q >> 1);
#pragma unroll
                for (int mt = 0; mt < 4; mt++) {
                    uint32_t ah[4], al[4];
                    int row = warp_m * 64 + mt * 16 + (q & 1) * 8 + r;
                    uint32_t addr = aBase + tile_off(row, aunit);
                    LDSM_X4(ah[0], ah[1], ah[2], ah[3], addr);
                    LDSM_X4(al[0], al[1], al[2], al[3], addr + TILE_B);

                    MMA_BF16(acc[mt][0], ah, bh0[0], bh0[1]);
                    MMA_BF16(acc[mt][1], ah, bh0[2], bh0[3]);
                    MMA_BF16(acc[mt][2], ah, bh1[0], bh1[1]);
                    MMA_BF16(acc[mt][3], ah, bh1[2], bh1[3]);

                    MMA_BF16(acc[mt][0], ah, bl0[0], bl0[1]);
                    MMA_BF16(acc[mt][1], ah, bl0[2], bl0[3]);
                    MMA_BF16(acc[mt][2], ah, bl1[0], bl1[1]);
                    MMA_BF16(acc[mt][3], ah, bl1[2], bl1[3]);

                    MMA_BF16(acc[mt][0], al, bh0[0], bh0[1]);
                    MMA_BF16(acc[mt][1], al, bh0[2], bh0[3]);
                    MMA_BF16(acc[mt][2], al, bh1[0], bh1[1]);
                    MMA_BF16(acc[mt][3], al, bh1[2], bh1[3]);
                }
            }
            stage = (stage + 1) % GEMM_STAGES;
        }

        // Epilogue (register-only reads; next tile's loads gated by top sync)
#pragma unroll
        for (int mt = 0; mt < 4; mt++) {
#pragma unroll
            for (int nt = 0; nt < 4; nt++) {
                int row = m0 + warp_m * 64 + mt * 16 + gp;
                int col = n0 + warp_n * 32 + nt * 8 + tg * 2;
                *(float2*)&C[(size_t)row * N + col] =
                    make_float2(acc[mt][nt][0], acc[mt][nt][1]);
                *(float2*)&C[(size_t)(row + 8) * N + col] =
                    make_float2(acc[mt][nt][2], acc[mt][nt][3]);
            }
        }
    }
}

// ---------------------------------------------------------------------------
// RoPE + bf16 hi/lo conversion of Q,K.  One block per sequence position s.
// ---------------------------------------------------------------------------
__global__ __launch_bounds__(256) void rope_cvt_kernel(
    const float* __restrict__ qkv,
    __nv_bfloat16* __restrict__ qhi, __nv_bfloat16* __restrict__ qlo,
    __nv_bfloat16* __restrict__ khi, __nv_bfloat16* __restrict__ klo)
{
    __shared__ float cs[64], sn[64];
    const int s = blockIdx.x;
    const int tid = threadIdx.x;
    if (tid < 64) {
        double inv = exp(-((double)(2 * tid) / (double)HD_) * 9.210340371976184);
        double ang = (double)s * inv;
        double sv, cv;
        sincos(ang, &sv, &cv);
        cs[tid] = (float)cv;
        sn[tid] = (float)sv;
    }
    __syncthreads();

#pragma unroll
    for (int it = 0; it < 10; it++) {
        int g = tid + it * 256;
        int d2 = g & 63;
        int head = g >> 6;          // 0..39
        size_t base = (size_t)s * QKV_O + head * HD_;
        float x1 = qkv[base + d2];
        float x2 = qkv[base + 64 + d2];
        float c = cs[d2], si = sn[d2];
        float y1 = x1 * c - x2 * si;
        float y2 = x1 * si + x2 * c;

        __nv_bfloat16 h1 = __float2bfloat16_rn(y1);
        __nv_bfloat16 l1 = __float2bfloat16_rn(y1 - __bfloat162float(h1));
        __nv_bfloat16 h2 = __float2bfloat16_rn(y2);
        __nv_bfloat16 l2 = __float2bfloat16_rn(y2 - __bfloat162float(h2));

        if (head < NH_) {
            size_t o = (size_t)s * H_ + head * HD_;
            qhi[o + d2] = h1; qlo[o + d2] = l1;
            qhi[o + 64 + d2] = h2; qlo[o + 64 + d2] = l2;
        } else {
            size_t o = (size_t)s * (NKV_ * HD_) + (head - NH_) * HD_;
            khi[o + d2] = h1; klo[o + d2] = l1;
            khi[o + 64 + d2] = h2; klo[o + 64 + d2] = l2;
        }
    }
}

// V: strided split-convert out of g_qkv
__global__ void v_cvt_kernel(const float* __restrict__ qkv,
                             __nv_bfloat16* __restrict__ vhi,
                             __nv_bfloat16* __restrict__ vlo)
{
    int i = blockIdx.x * blockDim.x + threadIdx.x;
    const int n4 = S_ * NKV_ * HD_ / 4;
    if (i >= n4) return;
    int s = i >> 8;
    int col = (i & 255) * 4;
    const float* src = qkv + (size_t)s * QKV_O + K_END + col;
    float4 v = *(const float4*)src;
    __nv_bfloat16 h0 = __float2bfloat16_rn(v.x);
    __nv_bfloat16 h1 = __float2bfloat16_rn(v.y);
    __nv_bfloat16 h2 = __float2bfloat16_rn(v.z);
    __nv_bfloat16 h3 = __float2bfloat16_rn(v.w);
    size_t o = (size_t)s * (NKV_ * HD_) + col;
    *(__nv_bfloat162*)(vhi + o)     = __nv_bfloat162(h0, h1);
    *(__nv_bfloat162*)(vhi + o + 2) = __nv_bfloat162(h2, h3);
    *(__nv_bfloat162*)(vlo + o) = __nv_bfloat162(
        __float2bfloat16_rn(v.x - __bfloat162float(h0)),
        __float2bfloat16_rn(v.y - __bfloat162float(h1)));
    *(__nv_bfloat162*)(vlo + o + 2) = __nv_bfloat162(
        __float2bfloat16_rn(v.z - __bfloat162float(h2)),
        __float2bfloat16_rn(v.w - __bfloat162float(h3)));
}

// ---------------------------------------------------------------------------
// Flash attention via mma.sync, bf16x3 QK^T and bf16x3 PV, causal, GQA.
// PERSISTENT CTAs with work-stealing; tiles ordered heavy-qb-first.
// Epilogue writes hi/lo bf16 split directly (feeds O-projection GEMM).
// ---------------------------------------------------------------------------
#define AP_ 136
#define APB_ 272
#define Q_COMP_B 17408
#define KV_COMP_B 8704
#define KV_STAGE_B (4 * KV_COMP_B)
#define ATTN_SMEM_BYTES (2 * Q_COMP_B + 2 * KV_STAGE_B)   // 104448

__global__ __launch_bounds__(128, 2) void flash_attn_mma_kernel(
    const __nv_bfloat16* __restrict__ qhi, const __nv_bfloat16* __restrict__ qlo,
    const __nv_bfloat16* __restrict__ khi, const __nv_bfloat16* __restrict__ klo,
    const __nv_bfloat16* __restrict__ vhi, const __nv_bfloat16* __restrict__ vlo,
    __nv_bfloat16* __restrict__ out_hi, __nv_bfloat16* __restrict__ out_lo,
    int total_tiles, unsigned* __restrict__ counter)
{
    extern __shared__ __align__(128) char smA[];
    __shared__ unsigned s_tile;
    const uint32_t sb = smem_u32(smA);
    const int tid = threadIdx.x;
    const int wid = tid >> 5;
    const int lane = tid & 31;
    const int gp = lane >> 2;
    const int tg = lane & 3;

    const uint32_t Qhi_s = sb;
    const uint32_t Qlo_s = sb + Q_COMP_B;
    const uint32_t Stage_s = sb + 2 * Q_COMP_B;
    const float scale = 0.08838834764831845f;

    for (;;) {
        if (tid == 0) s_tile = atomicAdd(counter, 1u);
        __syncthreads();                    // uniform + prev tile compute done
        const unsigned t = s_tile;
        if (t >= (unsigned)total_tiles) return;
        const int qb = (S_ / 64 - 1) - (int)(t >> 5);  // heavy first
        const int head = (int)(t & 31);
        const int kvh = head >> 2;
        const int q0 = qb * 64;

        // ---- load Q (one cp.async group)
#pragma unroll
        for (int i = 0; i < 16; i++) {
            int g = tid + i * 128;
            int comp = g >> 10;
            int rem = g & 1023;
            int row = rem >> 4;
            int u = rem & 15;
            const __nv_bfloat16* src = (comp ? qlo : qhi)
                + (size_t)(q0 + row) * H_ + head * HD_ + u * 8;
            uint32_t dst = (comp ? Qlo_s : Qhi_s) + (uint32_t)(row * APB_ + u * 16);
            CP_ASYNC16(dst, src);
        }
        CP_COMMIT();

        const int kb_max = 2 * qb + 1;

        auto load_kv = [&](int stage, int kb) {
            uint32_t st = Stage_s + (uint32_t)stage * KV_STAGE_B;
            const __nv_bfloat16* bases[4] = {khi, klo, vhi, vlo};
#pragma unroll
            for (int i = 0; i < 16; i++) {
                int g = tid + i * 128;
                int comp = g >> 9;
                int rem = g & 511;
                int row = rem >> 4;
                int u = rem & 15;
                const __nv_bfloat16* src = bases[comp]
                    + (size_t)(kb * 32 + row) * (NKV_ * HD_) + kvh * HD_ + u * 8;
                CP_ASYNC16(st + (uint32_t)(comp * KV_COMP_B + row * APB_ + u * 16), src);
            }
            CP_COMMIT();
        };

        load_kv(0, 0);

        float O[16][4];
        float m_i[2] = {-1e30f, -1e30f};
        float l_i[2] = {0.0f, 0.0f};
#pragma unroll
        for (int nt = 0; nt < 16; nt++)
#pragma unroll
            for (int e = 0; e < 4; e++) O[nt][e] = 0.0f;

        for (int kb = 0; kb <= kb_max; kb++) {
            if (kb < kb_max) { load_kv((kb + 1) & 1, kb + 1); CP_WAIT(1); }
            else             { CP_WAIT(0); }
            __syncthreads();

            const uint32_t st = Stage_s + (uint32_t)(kb & 1) * KV_STAGE_B;
            const uint32_t Ks_hi = st;
            const uint32_t Ks_lo = st + KV_COMP_B;
            const uint32_t Vs_hi = st + 2 * KV_COMP_B;
            const uint32_t Vs_lo = st + 3 * KV_COMP_B;

            float S[4][4];
#pragma unroll
            for (int tt = 0; tt < 4; tt++)
#pragma unroll
                for (int e = 0; e < 4; e++) S[tt][e] = 0.0f;

#pragma unroll
            for (int kt = 0; kt < 8; kt++) {
                uint32_t aoff = (uint32_t)((wid * 16 + (lane & 15)) * APB_
                                           + (kt * 16 + (lane >> 4) * 8) * 2);
                uint32_t ahi[4], alo[4];
                LDSM_X4(ahi[0], ahi[1], ahi[2], ahi[3], Qhi_s + aoff);
                LDSM_X4(alo[0], alo[1], alo[2], alo[3], Qlo_s + aoff);

                uint32_t bh[2][4], bl[2][4];
#pragma unroll
                for (int pr = 0; pr < 2; pr++) {
                    uint32_t boff = (uint32_t)((pr * 16 + (lane >> 4) * 8 + (lane & 7)) * APB_
                                               + (kt * 16 + ((lane >> 3) & 1) * 8) * 2);
                    LDSM_X4(bh[pr][0], bh[pr][1], bh[pr][2], bh[pr][3], Ks_hi + boff);
                    LDSM_X4(bl[pr][0], bl[pr][1], bl[pr][2], bl[pr][3], Ks_lo + boff);
                }
                MMA_BF16(S[0], ahi, bh[0][0], bh[0][1]);
                MMA_BF16(S[1], ahi, bh[0][2], bh[0][3]);
                MMA_BF16(S[2], ahi, bh[1][0], bh[1][1]);
                MMA_BF16(S[3], ahi, bh[1][2], bh[1][3]);

                MMA_BF16(S[0], ahi, bl[0][0], bl[0][1]);
                MMA_BF16(S[1], ahi, bl[0][2], bl[0][3]);
                MMA_BF16(S[2], ahi, bl[1][0], bl[1][1]);
                MMA_BF16(S[3], ahi, bl[1][2], bl[1][3]);

                MMA_BF16(S[0], alo, bh[0][0], bh[0][1]);
                MMA_BF16(S[1], alo, bh[0][2], bh[0][3]);
                MMA_BF16(S[2], alo, bh[1][0], bh[1][1]);
                MMA_BF16(S[3], alo, bh[1][2], bh[1][3]);
            }

            if (kb >= 2 * qb) {
#pragma unroll
                for (int tt = 0; tt < 4; tt++) {
                    int colb = kb * 32 + tt * 8 + 2 * tg;
#pragma unroll
                    for (int e = 0; e < 4; e++) {
                        int col = colb + (e & 1);
                        int row = q0 + wid * 16 + gp + ((e >= 2) ? 8 : 0);
                        S[tt][e] = (col <= row) ? S[tt][e] * scale : -1e30f;
                    }
                }
            } else {
#pragma unroll
                for (int tt = 0; tt < 4; tt++)
#pragma unroll
                    for (int e = 0; e < 4; e++) S[tt][e] *= scale;
            }

#pragma unroll
            for (int h = 0; h < 2; h++) {
                float mx = -1e30f;
#pragma unroll
                for (int tt = 0; tt < 4; tt++)
                    mx = fmaxf(mx, fmaxf(S[tt][2 * h], S[tt][2 * h + 1]));
                mx = fmaxf(mx, __shfl_xor_sync(0xffffffffu, mx, 1));
                mx = fmaxf(mx, __shfl_xor_sync(0xffffffffu, mx, 2));
                float m_new = fmaxf(m_i[h], mx);
                float alpha = __expf(m_i[h] - m_new);
                float sum = 0.0f;
#pragma unroll
                for (int tt = 0; tt < 4; tt++) {
                    S[tt][2 * h]     = __expf(S[tt][2 * h] - m_new);
                    S[tt][2 * h + 1] = __expf(S[tt][2 * h + 1] - m_new);
                    sum += S[tt][2 * h] + S[tt][2 * h + 1];
                }
                sum += __shfl_xor_sync(0xffffffffu, sum, 1);
                sum += __shfl_xor_sync(0xffffffffu, sum, 2);
                l_i[h] = l_i[h] * alpha + sum;
                m_i[h] = m_new;
#pragma unroll
                for (int nt = 0; nt < 16; nt++) {
                    O[nt][2 * h] *= alpha;
                    O[nt][2 * h + 1] *= alpha;
                }
            }

#pragma unroll
            for (int kt2 = 0; kt2 < 2; kt2++) {
                uint32_t phi[4], plo[4];
                {
                    float* p0 = S[2 * kt2];
                    float* p1 = S[2 * kt2 + 1];
                    float h00 = __bfloat162float(__float2bfloat16_rn(p0[0]));
                    float h01 = __bfloat162float(__float2bfloat16_rn(p0[1]));
                    float h02 = __bfloat162float(__float2bfloat16_rn(p0[2]));
                    float h03 = __bfloat162float(__float2bfloat16_rn(p0[3]));
                    float h10 = __bfloat162float(__float2bfloat16_rn(p1[0]));
                    float h11 = __bfloat162float(__float2bfloat16_rn(p1[1]));
                    float h12 = __bfloat162float(__float2bfloat16_rn(p1[2]));
                    float h13 = __bfloat162float(__float2bfloat16_rn(p1[3]));
                    phi[0] = pack_bf16(h00, h01);
                    phi[1] = pack_bf16(h02, h03);
                    phi[2] = pack_bf16(h10, h11);
                    phi[3] = pack_bf16(h12, h13);
                    plo[0] = pack_bf16(p0[0] - h00, p0[1] - h01);
                    plo[1] = pack_bf16(p0[2] - h02, p0[3] - h03);
                    plo[2] = pack_bf16(p1[0] - h10, p1[1] - h11);
                    plo[3] = pack_bf16(p1[2] - h12, p1[3] - h13);
                }
#pragma unroll
                for (int dq = 0; dq < 4; dq++) {
                    uint32_t bh0[4], bl0[4], bh1[4], bl1[4];
#pragma unroll
                    for (int half = 0; half < 2; half++) {
                        int dp = 2 * dq + half;
                        uint32_t voff = (uint32_t)((kt2 * 16 + ((lane >> 3) & 1) * 8 + (lane & 7)) * APB_
                                                   + (dp * 16 + (lane >> 4) * 8) * 2);
                        if (half == 0) {
                            LDSM_X4_T(bh0[0], bh0[1], bh0[2], bh0[3], Vs_hi + voff);
                            LDSM_X4_T(bl0[0], bl0[1], bl0[2], bl0[3], Vs_lo + voff);
                        } else {
                            LDSM_X4_T(bh1[0], bh1[1], bh1[2], bh1[3], Vs_hi + voff);
                            LDSM_X4_T(bl1[0], bl1[1], bl1[2], bl1[3], Vs_lo + voff);
                        }
                    }
                    float* O0 = O[4 * dq + 0];
                    float* O1 = O[4 * dq + 1];
                    float* O2 = O[4 * dq + 2];
                    float* O3 = O[4 * dq + 3];
                    MMA_BF16(O0, phi, bh0[0], bh0[1]);
                    MMA_BF16(O1, phi, bh0[2], bh0[3]);
                    MMA_BF16(O2, phi, bh1[0], bh1[1]);
                    MMA_BF16(O3, phi, bh1[2], bh1[3]);

                    MMA_BF16(O0, phi, bl0[0], bl0[1]);
                    MMA_BF16(O1, phi, bl0[2], bl0[3]);
                    MMA_BF16(O2, phi, bl1[0], bl1[1]);
                    MMA_BF16(O3, phi, bl1[2], bl1[3]);

                    MMA_BF16(O0, plo, bh0[0], bh0[1]);
                    MMA_BF16(O1, plo, bh0[2], bh0[3]);
                    MMA_BF16(O2, plo, bh1[0], bh1[1]);
                    MMA_BF16(O3, plo, bh1[2], bh1[3]);
                }
            }
            __syncthreads();
        }

        // ---- finalize + write bf16 hi/lo split directly (register-only)
#pragma unroll
        for (int h = 0; h < 2; h++) {
            float inv = 1.0f / l_i[h];
            int row = q0 + wid * 16 + gp + h * 8;
            size_t base = (size_t)row * H_ + head * HD_;
#pragma unroll
            for (int nt = 0; nt < 16; nt++) {
                float o0 = O[nt][2 * h] * inv;
                float o1 = O[nt][2 * h + 1] * inv;
                float hh0 = __bfloat162float(__float2bfloat16_rn(o0));
                float hh1 = __bfloat162float(__float2bfloat16_rn(o1));
                size_t off = base + nt * 8 + 2 * tg;
                *(uint32_t*)(out_hi + off) = pack_bf16(hh0, hh1);
                *(uint32_t*)(out_lo + off) = pack_bf16(o0 - hh0, o1 - hh1);
            }
        }
    }
}

// ---------------------------------------------------------------------------
extern "C" void kernel_launch(void* const* d_in, const int* in_sizes, int n_in,
                              void* d_out, int out_size)
{
    const float* hidden = (const float*)d_in[0];   // [1,2048,4096]
    const float* Wqkv   = (const float*)d_in[1];   // [6144,4096]
    const float* Wo     = (const float*)d_in[2];   // [4096,4096]
    float* out = (float*)d_out;                    // [1,2048,4096]

    float* qkv_ptr = nullptr;
    __nv_bfloat16 *hid_hi, *hid_lo, *wqkv_hi, *wqkv_lo, *wo_hi, *wo_lo, *attn_hi, *attn_lo;
    __nv_bfloat16 *q_hi, *q_lo, *k_hi, *k_lo, *v_hi, *v_lo;
    unsigned* counters;
    cudaGetSymbolAddress((void**)&qkv_ptr, g_qkv);
    cudaGetSymbolAddress((void**)&hid_hi, g_hid_hi);
    cudaGetSymbolAddress((void**)&hid_lo, g_hid_lo);
    cudaGetSymbolAddress((void**)&wqkv_hi, g_wqkv_hi);
    cudaGetSymbolAddress((void**)&wqkv_lo, g_wqkv_lo);
    cudaGetSymbolAddress((void**)&wo_hi, g_wo_hi);
    cudaGetSymbolAddress((void**)&wo_lo, g_wo_lo);
    cudaGetSymbolAddress((void**)&attn_hi, g_attn_hi);
    cudaGetSymbolAddress((void**)&attn_lo, g_attn_lo);
    cudaGetSymbolAddress((void**)&q_hi, g_q_hi);
    cudaGetSymbolAddress((void**)&q_lo, g_q_lo);
    cudaGetSymbolAddress((void**)&k_hi, g_k_hi);
    cudaGetSymbolAddress((void**)&k_lo, g_k_lo);
    cudaGetSymbolAddress((void**)&v_hi, g_v_hi);
    cudaGetSymbolAddress((void**)&v_lo, g_v_lo);
    cudaGetSymbolAddress((void**)&counters, g_counters);

    int smCount = 148;
    cudaDeviceGetAttribute(&smCount, cudaDevAttrMultiProcessorCount, 0);
    const int gemm_grid = 2 * smCount;
    const int attn_grid = 2 * smCount;

    cudaFuncSetAttribute(gemm_mma_kernel,
                         cudaFuncAttributeMaxDynamicSharedMemorySize, GEMM_SMEM_BYTES);
    cudaFuncSetAttribute(flash_attn_mma_kernel,
                         cudaFuncAttributeMaxDynamicSharedMemorySize, ATTN_SMEM_BYTES);

    // reset work-stealing counters
    cudaMemsetAsync(counters, 0, 4 * sizeof(unsigned));

    // 0) split-convert inputs
    {
        int n4;
        n4 = (S_ * H_) / 4;
        cvt_split_kernel<<<(n4 + 255) / 256, 256>>>(hidden, hid_hi, hid_lo, n4);
        n4 = (QKV_O * H_) / 4;
        cvt_split_kernel<<<(n4 + 255) / 256, 256>>>(Wqkv, wqkv_hi, wqkv_lo, n4);
        n4 = (H_ * H_) / 4;
        cvt_split_kernel<<<(n4 + 255) / 256, 256>>>(Wo, wo_hi, wo_lo, n4);
    }

    // 1) QKV projection (HMMA bf16x3), persistent + work-stealing
    {
        int mt = S_ / 128, nt = QKV_O / 128;
        gemm_mma_kernel<<<gemm_grid, 256, GEMM_SMEM_BYTES>>>(
            hid_hi, hid_lo, wqkv_hi, wqkv_lo, qkv_ptr, QKV_O, H_, mt, mt * nt,
            counters + 0);
    }

    // 2) RoPE + split-convert Q,K; split-convert V
    {
        rope_cvt_kernel<<<S_, 256>>>(qkv_ptr, q_hi, q_lo, k_hi, k_lo);
        int n4 = (S_ * NKV_ * HD_) / 4;
        v_cvt_kernel<<<(n4 + 255) / 256, 256>>>(qkv_ptr, v_hi, v_lo);
    }

    // 3) Flash attention (HMMA bf16x3), persistent + work-stealing
    {
        int tiles = (S_ / 64) * NH_;   // 1024
        flash_attn_mma_kernel<<<attn_grid, 128, ATTN_SMEM_BYTES>>>(
            q_hi, q_lo, k_hi, k_lo, v_hi, v_lo, attn_hi, attn_lo,
            tiles, counters + 1);
    }

    // 4) Output projection (HMMA bf16x3), persistent + work-stealing
    {
        int mt = S_ / 128, nt = H_ / 128;
        gemm_mma_kernel<<<gemm_grid, 256, GEMM_SMEM_BYTES>>>(
            attn_hi, attn_lo, wo_hi, wo_lo, out, H_, H_, mt, mt * nt,
            counters + 2);
    }
}